// round 6
// baseline (speedup 1.0000x reference)
#include <cuda_runtime.h>
#include <cuda_fp16.h>

#define MAX_NODES 100000
#define MAX_EDGES 1600000
#define D 64

// ---- static device scratch (no allocations allowed) ----
__device__ float   g_deg[MAX_NODES];
__device__ float   g_dis[MAX_NODES];
__device__ int     g_counts[MAX_NODES];
__device__ int     g_row_start[MAX_NODES];
__device__ int     g_cursor[MAX_NODES];
__device__ int     g_block_sums[1024];
__device__ int2    g_edge[MAX_EDGES];          // {src, norm bits}
__device__ __half2 g_hA[MAX_NODES * 32];       // feature ping
__device__ __half2 g_hB[MAX_NODES * 32];       // feature pong
__device__ int     g_is32;

// ---------------------------------------------------------------------------
__global__ void k_init(int n) {
    int i = blockIdx.x * blockDim.x + threadIdx.x;
    if (i == 0) g_is32 = 0;
    if (i < n) { g_deg[i] = 1.0f; g_counts[i] = 0; }   // self-loop weight 1
}

// Probe dtype: an int32 buffer read as int64 packs two ids -> values >= 2^32.
__global__ void k_detect(const long long* __restrict__ ei, int E, int n) {
    int i = threadIdx.x;
    if (i < E) {
        long long v = ei[i];
        if (v < 0 || v >= (long long)n) atomicOr(&g_is32, 1);
    }
}

// x fp32 -> fp16 (independent of graph build)
__global__ void k_convert_x(const float* __restrict__ x, int nv) {
    int i = blockIdx.x * blockDim.x + threadIdx.x;   // half2 elements
    if (i < nv) {
        float2 v = ((const float2*)x)[i];
        g_hA[i] = __floats2half2_rn(v.x, v.y);
    }
}

__device__ __forceinline__ int load_idx(const void* ei, int pos, int is32, int n) {
    int v;
    if (is32) v = ((const int*)ei)[pos];
    else      v = (int)((const long long*)ei)[pos];
    return v < 0 ? 0 : (v >= n ? n - 1 : v);
}

__global__ void k_edge_deg(const void* __restrict__ ei,
                           const float* __restrict__ w, int E, int n) {
    int e = blockIdx.x * blockDim.x + threadIdx.x;
    if (e < E) {
        int is32 = g_is32;
        int dst = load_idx(ei, E + e, is32, n);
        atomicAdd(&g_deg[dst], w[e]);
        atomicAdd(&g_counts[dst], 1);
    }
}

// --- exclusive scan of g_counts -> g_row_start; also computes dis ---
__global__ void k_scan_local(int n) {
    __shared__ int sh[1024];
    int tid = threadIdx.x;
    int gid = blockIdx.x * 1024 + tid;
    int v = (gid < n) ? g_counts[gid] : 0;
    if (gid < n) g_dis[gid] = rsqrtf(g_deg[gid]);    // deg >= 1 always
    sh[tid] = v;
    __syncthreads();
    for (int off = 1; off < 1024; off <<= 1) {
        int t = (tid >= off) ? sh[tid - off] : 0;
        __syncthreads();
        sh[tid] += t;
        __syncthreads();
    }
    if (gid < n) g_row_start[gid] = sh[tid] - v;
    if (tid == 1023) g_block_sums[blockIdx.x] = sh[1023];
}

__global__ void k_scan_top(int nb) {
    __shared__ int sh[1024];
    int tid = threadIdx.x;
    int v = (tid < nb) ? g_block_sums[tid] : 0;
    sh[tid] = v;
    __syncthreads();
    for (int off = 1; off < 1024; off <<= 1) {
        int t = (tid >= off) ? sh[tid - off] : 0;
        __syncthreads();
        sh[tid] += t;
        __syncthreads();
    }
    if (tid < nb) g_block_sums[tid] = sh[tid] - v;
}

__global__ void k_scan_add(int n) {
    int gid = blockIdx.x * 1024 + threadIdx.x;
    if (gid < n) {
        int s = g_row_start[gid] + g_block_sums[blockIdx.x];
        g_row_start[gid] = s;
        g_cursor[gid]    = s;
    }
}

// --- CSR-by-dst scatter with packed (src, norm) 8B record ---
__global__ void k_build(const void* __restrict__ ei,
                        const float* __restrict__ w, int E, int n) {
    int e = blockIdx.x * blockDim.x + threadIdx.x;
    if (e < E) {
        int is32 = g_is32;
        int s = load_idx(ei, e, is32, n);
        int d = load_idx(ei, E + e, is32, n);
        int pos = atomicAdd(&g_cursor[d], 1);
        float nm = g_dis[s] * w[e] * g_dis[d];
        g_edge[pos] = make_int2(s, __float_as_int(nm));
    }
}

// --- fused gather + GEMM + bias (+relu) per layer ---
// io_mode: 0 = hA -> hB (relu), 1 = hB -> hA (relu), 2 = hA -> outf (no relu)
// 256 threads / 128 nodes per block. Warp gathers 16 nodes into a shared
// fp16 A-tile, then block computes A @ W with 4x8 register tiles.
__global__ void __launch_bounds__(256) k_fused(
    const float* __restrict__ W, const float* __restrict__ b,
    float* __restrict__ outf, int io_mode, int n)
{
    const __half2* hin = (io_mode == 1) ? g_hB : g_hA;   // device-side resolve
    __half2* outh = (io_mode == 0) ? g_hB : (io_mode == 1 ? g_hA : nullptr);
    int relu = (io_mode != 2);

    __shared__ __half2 Ash[128][33];   // [row][col-pair], padded
    __shared__ float   Wsh[64][64];    // [k][c] 16KB
    int tid  = threadIdx.x;
    int warp = tid >> 5;
    int lane = tid & 31;
    int base = blockIdx.x * 128;

    for (int i = tid; i < 4096; i += 256)
        Wsh[i >> 6][i & 63] = W[i];

    // ---- gather phase: each warp aggregates 16 nodes ----
    for (int i = 0; i < 16; i++) {
        int r = warp * 16 + i;
        int node = base + r;
        float2 acc = make_float2(0.f, 0.f);
        if (node < n) {
            float dd = g_dis[node];
            dd *= dd;
            float2 sv = __half22float2(hin[node * 32 + lane]);
            acc.x = sv.x * dd; acc.y = sv.y * dd;
            int e   = g_row_start[node];
            int end = g_cursor[node];
            while (e + 2 <= end) {
                int2 e0 = g_edge[e];
                int2 e1 = g_edge[e + 1];
                float2 v0 = __half22float2(hin[e0.x * 32 + lane]);
                float2 v1 = __half22float2(hin[e1.x * 32 + lane]);
                float n0 = __int_as_float(e0.y);
                float n1 = __int_as_float(e1.y);
                acc.x += v0.x * n0; acc.y += v0.y * n0;
                acc.x += v1.x * n1; acc.y += v1.y * n1;
                e += 2;
            }
            if (e < end) {
                int2 e0 = g_edge[e];
                float2 v0 = __half22float2(hin[e0.x * 32 + lane]);
                float n0 = __int_as_float(e0.y);
                acc.x += v0.x * n0; acc.y += v0.y * n0;
            }
        }
        Ash[r][lane] = __floats2half2_rn(acc.x, acc.y);
    }
    __syncthreads();

    // ---- GEMM phase: 4 rows x 8 cols per thread ----
    int r0 = (tid >> 3) << 2;   // 0,4,...,124
    int c0 = (tid & 7) << 3;    // 0,8,...,56

    float acc[4][8];
#pragma unroll
    for (int i = 0; i < 4; i++)
#pragma unroll
        for (int j = 0; j < 8; j++) acc[i][j] = 0.f;

#pragma unroll 4
    for (int k2 = 0; k2 < 32; k2++) {
        float2 a[4];
#pragma unroll
        for (int i = 0; i < 4; i++) a[i] = __half22float2(Ash[r0 + i][k2]);
        float4 we0 = *(const float4*)&Wsh[2 * k2][c0];
        float4 we1 = *(const float4*)&Wsh[2 * k2][c0 + 4];
        float4 wo0 = *(const float4*)&Wsh[2 * k2 + 1][c0];
        float4 wo1 = *(const float4*)&Wsh[2 * k2 + 1][c0 + 4];
#pragma unroll
        for (int i = 0; i < 4; i++) {
            acc[i][0] += a[i].x * we0.x + a[i].y * wo0.x;
            acc[i][1] += a[i].x * we0.y + a[i].y * wo0.y;
            acc[i][2] += a[i].x * we0.z + a[i].y * wo0.z;
            acc[i][3] += a[i].x * we0.w + a[i].y * wo0.w;
            acc[i][4] += a[i].x * we1.x + a[i].y * wo1.x;
            acc[i][5] += a[i].x * we1.y + a[i].y * wo1.y;
            acc[i][6] += a[i].x * we1.z + a[i].y * wo1.z;
            acc[i][7] += a[i].x * we1.w + a[i].y * wo1.w;
        }
    }

    float4 b0 = *(const float4*)&b[c0];
    float4 b1 = *(const float4*)&b[c0 + 4];
    float bb[8] = {b0.x, b0.y, b0.z, b0.w, b1.x, b1.y, b1.z, b1.w};

#pragma unroll
    for (int i = 0; i < 4; i++) {
        int grow = base + r0 + i;
        if (grow >= n) continue;
        float v[8];
#pragma unroll
        for (int j = 0; j < 8; j++) {
            float t = acc[i][j] + bb[j];
            v[j] = relu ? fmaxf(t, 0.f) : t;
        }
        if (outh) {
            __half2* dst = &outh[grow * 32 + (c0 >> 1)];
            dst[0] = __floats2half2_rn(v[0], v[1]);
            dst[1] = __floats2half2_rn(v[2], v[3]);
            dst[2] = __floats2half2_rn(v[4], v[5]);
            dst[3] = __floats2half2_rn(v[6], v[7]);
        } else {
            float4* dst = (float4*)&outf[grow * 64 + c0];
            dst[0] = make_float4(v[0], v[1], v[2], v[3]);
            dst[1] = make_float4(v[4], v[5], v[6], v[7]);
        }
    }
}

// ---------------------------------------------------------------------------
extern "C" void kernel_launch(void* const* d_in, const int* in_sizes, int n_in,
                              void* d_out, int out_size) {
    const float* x  = (const float*)d_in[0];
    const void*  ei = d_in[1];
    const float* w  = (const float*)d_in[2];
    const float* W1 = (const float*)d_in[3];
    const float* b1 = (const float*)d_in[4];
    const float* W2 = (const float*)d_in[5];
    const float* b2 = (const float*)d_in[6];
    const float* W3 = (const float*)d_in[7];
    const float* b3 = (const float*)d_in[8];
    float* out = (float*)d_out;

    int n = in_sizes[0] / D;      // 100000
    int E = in_sizes[1] / 2;      // 1600000

    const int tb = 256;
    int nblk_n = (n + tb - 1) / tb;
    int nblk_e = (E + tb - 1) / tb;
    int nblk_c = (n * 32 + tb - 1) / tb;
    int nb = (n + 1023) / 1024;

    k_init<<<nblk_n, tb>>>(n);
    k_detect<<<1, 256>>>((const long long*)ei, E, n);
    k_convert_x<<<nblk_c, tb>>>(x, n * 32);
    k_edge_deg<<<nblk_e, tb>>>(ei, w, E, n);
    k_scan_local<<<nb, 1024>>>(n);
    k_scan_top<<<1, 1024>>>(nb);
    k_scan_add<<<nb, 1024>>>(n);
    k_build<<<nblk_e, tb>>>(ei, w, E, n);

    int fblocks = (n + 127) / 128;
    // layer1: hA(x16) -> hB ; layer2: hB -> hA ; layer3: hA -> out(fp32)
    k_fused<<<fblocks, 256>>>(W1, b1, nullptr, 0, n);
    k_fused<<<fblocks, 256>>>(W2, b2, nullptr, 1, n);
    k_fused<<<fblocks, 256>>>(W3, b3, out, 2, n);
}

// round 7
// speedup vs baseline: 1.1184x; 1.1184x over previous
#include <cuda_runtime.h>
#include <cuda_fp16.h>

#define MAX_NODES 100000
#define MAX_EDGES 1600000
#define D 64

// ---- static device scratch (no allocations allowed) ----
__device__ float   g_deg[MAX_NODES];
__device__ float   g_dis[MAX_NODES];
__device__ int     g_counts[MAX_NODES];
__device__ int     g_row_start[MAX_NODES];
__device__ int     g_cursor[MAX_NODES];
__device__ int     g_block_sums[1024];
__device__ int2    g_edge[MAX_EDGES];          // {src, norm bits}
__device__ __half2 g_hA[MAX_NODES * 32];       // feature ping
__device__ __half2 g_hB[MAX_NODES * 32];       // feature pong
__device__ __half2 g_agg16[MAX_NODES * 32];    // aggregation result (fp16)
__device__ int     g_is32;

// ---------------------------------------------------------------------------
__global__ void k_init(int n) {
    int i = blockIdx.x * blockDim.x + threadIdx.x;
    if (i == 0) g_is32 = 0;
    if (i < n) { g_deg[i] = 1.0f; g_counts[i] = 0; }   // self-loop weight 1
}

// Probe dtype: an int32 buffer read as int64 packs two ids -> values >= 2^32.
__global__ void k_detect(const long long* __restrict__ ei, int E, int n) {
    int i = threadIdx.x;
    if (i < E) {
        long long v = ei[i];
        if (v < 0 || v >= (long long)n) atomicOr(&g_is32, 1);
    }
}

// x fp32 -> fp16
__global__ void k_convert_x(const float* __restrict__ x, int nv) {
    int i = blockIdx.x * blockDim.x + threadIdx.x;   // half2 elements
    if (i < nv) {
        float2 v = ((const float2*)x)[i];
        g_hA[i] = __floats2half2_rn(v.x, v.y);
    }
}

__device__ __forceinline__ int load_idx(const void* ei, int pos, int is32, int n) {
    int v;
    if (is32) v = ((const int*)ei)[pos];
    else      v = (int)((const long long*)ei)[pos];
    return v < 0 ? 0 : (v >= n ? n - 1 : v);
}

__global__ void k_edge_deg(const void* __restrict__ ei,
                           const float* __restrict__ w, int E, int n) {
    int e = blockIdx.x * blockDim.x + threadIdx.x;
    if (e < E) {
        int is32 = g_is32;
        int dst = load_idx(ei, E + e, is32, n);
        atomicAdd(&g_deg[dst], w[e]);
        atomicAdd(&g_counts[dst], 1);
    }
}

// --- exclusive scan of g_counts -> g_row_start; also computes dis ---
__global__ void k_scan_local(int n) {
    __shared__ int sh[1024];
    int tid = threadIdx.x;
    int gid = blockIdx.x * 1024 + tid;
    int v = (gid < n) ? g_counts[gid] : 0;
    if (gid < n) g_dis[gid] = rsqrtf(g_deg[gid]);    // deg >= 1 always
    sh[tid] = v;
    __syncthreads();
    for (int off = 1; off < 1024; off <<= 1) {
        int t = (tid >= off) ? sh[tid - off] : 0;
        __syncthreads();
        sh[tid] += t;
        __syncthreads();
    }
    if (gid < n) g_row_start[gid] = sh[tid] - v;
    if (tid == 1023) g_block_sums[blockIdx.x] = sh[1023];
}

__global__ void k_scan_top(int nb) {
    __shared__ int sh[1024];
    int tid = threadIdx.x;
    int v = (tid < nb) ? g_block_sums[tid] : 0;
    sh[tid] = v;
    __syncthreads();
    for (int off = 1; off < 1024; off <<= 1) {
        int t = (tid >= off) ? sh[tid - off] : 0;
        __syncthreads();
        sh[tid] += t;
        __syncthreads();
    }
    if (tid < nb) g_block_sums[tid] = sh[tid] - v;
}

__global__ void k_scan_add(int n) {
    int gid = blockIdx.x * 1024 + threadIdx.x;
    if (gid < n) {
        int s = g_row_start[gid] + g_block_sums[blockIdx.x];
        g_row_start[gid] = s;
        g_cursor[gid]    = s;
    }
}

// --- CSR-by-dst scatter with packed (src, norm) 8B record ---
__global__ void k_build(const void* __restrict__ ei,
                        const float* __restrict__ w, int E, int n) {
    int e = blockIdx.x * blockDim.x + threadIdx.x;
    if (e < E) {
        int is32 = g_is32;
        int s = load_idx(ei, e, is32, n);
        int d = load_idx(ei, E + e, is32, n);
        int pos = atomicAdd(&g_cursor[d], 1);
        float nm = g_dis[s] * w[e] * g_dis[d];
        g_edge[pos] = make_int2(s, __float_as_int(nm));
    }
}

// --- aggregation: one warp per node, fp16 rows (128B), 4-wide edge unroll ---
// io_mode: 0/2 read g_hA, 1 read g_hB. Writes g_agg16.
__global__ void k_gather(int io_mode, int n) {
    const __half2* hin = (io_mode == 1) ? g_hB : g_hA;
    int node = (blockIdx.x * blockDim.x + threadIdx.x) >> 5;
    int lane = threadIdx.x & 31;
    if (node >= n) return;

    float dd = g_dis[node];
    dd *= dd;
    float2 sv = __half22float2(hin[node * 32 + lane]);
    float ax = sv.x * dd, ay = sv.y * dd;

    int e   = g_row_start[node];
    int end = g_cursor[node];
    for (; e + 4 <= end; e += 4) {
        int2 e0 = g_edge[e];
        int2 e1 = g_edge[e + 1];
        int2 e2 = g_edge[e + 2];
        int2 e3 = g_edge[e + 3];
        float2 v0 = __half22float2(hin[e0.x * 32 + lane]);
        float2 v1 = __half22float2(hin[e1.x * 32 + lane]);
        float2 v2 = __half22float2(hin[e2.x * 32 + lane]);
        float2 v3 = __half22float2(hin[e3.x * 32 + lane]);
        float n0 = __int_as_float(e0.y), n1 = __int_as_float(e1.y);
        float n2 = __int_as_float(e2.y), n3 = __int_as_float(e3.y);
        ax += v0.x * n0; ay += v0.y * n0;
        ax += v1.x * n1; ay += v1.y * n1;
        ax += v2.x * n2; ay += v2.y * n2;
        ax += v3.x * n3; ay += v3.y * n3;
    }
    for (; e < end; e++) {
        int2 e0 = g_edge[e];
        float2 v0 = __half22float2(hin[e0.x * 32 + lane]);
        float n0 = __int_as_float(e0.y);
        ax += v0.x * n0; ay += v0.y * n0;
    }
    g_agg16[node * 32 + lane] = __floats2half2_rn(ax, ay);
}

// --- GEMM (agg16 @ W) + bias (+relu): 128 rows/block, 256 thr, 4x8 tile ---
// io_mode: 0 -> g_hB (relu), 1 -> g_hA (relu), 2 -> outf fp32 (no relu)
__global__ void __launch_bounds__(256) k_gemm(
    const float* __restrict__ W, const float* __restrict__ b,
    float* __restrict__ outf, int io_mode, int n)
{
    __half2* outh = (io_mode == 0) ? g_hB : (io_mode == 1 ? g_hA : nullptr);
    int relu = (io_mode != 2);

    __shared__ float Wsh[64][64];    // [k][c]  16KB
    __shared__ float At[64][128];    // [k][r]  32KB (transposed A tile)
    int tid  = threadIdx.x;
    int row0 = blockIdx.x * 128;

    for (int i = tid; i < 4096; i += 256)
        Wsh[i >> 6][i & 63] = W[i];

    // load 128x64 fp16 A tile, transposed into At (fp32)
    {
        int r = tid >> 1;                 // 0..127
        int h = (tid & 1) * 16;           // half2-column half: 0 or 16
        int grow = row0 + r;
        const __half2* src = &g_agg16[grow * 32 + h];
#pragma unroll
        for (int j = 0; j < 16; j++) {
            float2 v = (grow < n) ? __half22float2(src[j])
                                  : make_float2(0.f, 0.f);
            int c = (h + j) * 2;
            At[c][r] = v.x; At[c + 1][r] = v.y;
        }
    }
    __syncthreads();

    int r0 = (tid >> 3) << 2;   // 0,4,...,124
    int c0 = (tid & 7) << 3;    // 0,8,...,56

    float acc[4][8];
#pragma unroll
    for (int i = 0; i < 4; i++)
#pragma unroll
        for (int j = 0; j < 8; j++) acc[i][j] = 0.f;

#pragma unroll 8
    for (int k = 0; k < 64; k++) {
        float4 a  = *(const float4*)&At[k][r0];
        float4 w0 = *(const float4*)&Wsh[k][c0];
        float4 w1 = *(const float4*)&Wsh[k][c0 + 4];
        float av[4] = {a.x, a.y, a.z, a.w};
#pragma unroll
        for (int i = 0; i < 4; i++) {
            acc[i][0] += av[i] * w0.x; acc[i][1] += av[i] * w0.y;
            acc[i][2] += av[i] * w0.z; acc[i][3] += av[i] * w0.w;
            acc[i][4] += av[i] * w1.x; acc[i][5] += av[i] * w1.y;
            acc[i][6] += av[i] * w1.z; acc[i][7] += av[i] * w1.w;
        }
    }

    float4 b0 = *(const float4*)&b[c0];
    float4 b1 = *(const float4*)&b[c0 + 4];
    float bb[8] = {b0.x, b0.y, b0.z, b0.w, b1.x, b1.y, b1.z, b1.w};

#pragma unroll
    for (int i = 0; i < 4; i++) {
        int grow = row0 + r0 + i;
        if (grow >= n) continue;
        float v[8];
#pragma unroll
        for (int j = 0; j < 8; j++) {
            float t = acc[i][j] + bb[j];
            v[j] = relu ? fmaxf(t, 0.f) : t;
        }
        if (outh) {
            __half2* dst = &outh[grow * 32 + (c0 >> 1)];
            dst[0] = __floats2half2_rn(v[0], v[1]);
            dst[1] = __floats2half2_rn(v[2], v[3]);
            dst[2] = __floats2half2_rn(v[4], v[5]);
            dst[3] = __floats2half2_rn(v[6], v[7]);
        } else {
            float4* dst = (float4*)&outf[grow * 64 + c0];
            dst[0] = make_float4(v[0], v[1], v[2], v[3]);
            dst[1] = make_float4(v[4], v[5], v[6], v[7]);
        }
    }
}

// ---------------------------------------------------------------------------
extern "C" void kernel_launch(void* const* d_in, const int* in_sizes, int n_in,
                              void* d_out, int out_size) {
    const float* x  = (const float*)d_in[0];
    const void*  ei = d_in[1];
    const float* w  = (const float*)d_in[2];
    const float* W1 = (const float*)d_in[3];
    const float* b1 = (const float*)d_in[4];
    const float* W2 = (const float*)d_in[5];
    const float* b2 = (const float*)d_in[6];
    const float* W3 = (const float*)d_in[7];
    const float* b3 = (const float*)d_in[8];
    float* out = (float*)d_out;

    int n = in_sizes[0] / D;      // 100000
    int E = in_sizes[1] / 2;      // 1600000

    const int tb = 256;
    int nblk_n = (n + tb - 1) / tb;
    int nblk_e = (E + tb - 1) / tb;
    int nblk_c = (n * 32 + tb - 1) / tb;
    int nb = (n + 1023) / 1024;

    k_init<<<nblk_n, tb>>>(n);
    k_detect<<<1, 256>>>((const long long*)ei, E, n);
    k_convert_x<<<nblk_c, tb>>>(x, n * 32);
    k_edge_deg<<<nblk_e, tb>>>(ei, w, E, n);
    k_scan_local<<<nb, 1024>>>(n);
    k_scan_top<<<1, 1024>>>(nb);
    k_scan_add<<<nb, 1024>>>(n);
    k_build<<<nblk_e, tb>>>(ei, w, E, n);

    int gblocks = (n * 32 + tb - 1) / tb;   // one warp per node
    int mblocks = (n + 127) / 128;

    // layer1: hA(x16) -> agg -> hB ; layer2: hB -> agg -> hA ; layer3: hA -> out
    k_gather<<<gblocks, tb>>>(0, n);
    k_gemm<<<mblocks, 256>>>(W1, b1, nullptr, 0, n);
    k_gather<<<gblocks, tb>>>(1, n);
    k_gemm<<<mblocks, 256>>>(W2, b2, nullptr, 1, n);
    k_gather<<<gblocks, tb>>>(0, n);
    k_gemm<<<mblocks, 256>>>(W3, b3, out, 2, n);
}

// round 8
// speedup vs baseline: 1.1888x; 1.0629x over previous
#include <cuda_runtime.h>
#include <cuda_fp16.h>
#include <mma.h>

using namespace nvcuda;

#define MAX_NODES 100000
#define MAX_EDGES 1600000
#define D 64

// ---- static device scratch (no allocations allowed) ----
__device__ float   g_deg[MAX_NODES];
__device__ float   g_dis[MAX_NODES];
__device__ int     g_counts[MAX_NODES];
__device__ int     g_row_start[MAX_NODES];
__device__ int     g_cursor[MAX_NODES];
__device__ int     g_block_sums[1024];
__device__ int2    g_edge[MAX_EDGES];               // {src, norm bits}
__device__ __half2 g_hA[MAX_NODES * 32];            // feature ping
__device__ __half2 g_hB[MAX_NODES * 32];            // feature pong
__device__ __half2 g_agg16[(MAX_NODES + 128) * 32]; // agg (fp16), padded for wmma tiles
__device__ int     g_is32;

// --- merged: init deg/counts + dtype detect + x fp32->fp16 convert ---
__global__ void k_prep(const float* __restrict__ x, const long long* __restrict__ ei,
                       int n, int nv) {
    int i = blockIdx.x * blockDim.x + threadIdx.x;
    if (i < nv) {
        float2 v = ((const float2*)x)[i];
        g_hA[i] = __floats2half2_rn(v.x, v.y);
    }
    if (i < n) { g_deg[i] = 1.0f; g_counts[i] = 0; }   // self-loop weight 1
    if (i < 256) {
        // int32 buffer read as int64 packs two ids -> values >= 2^32
        long long v = ei[i];
        if (v < 0 || v >= (long long)n) atomicOr(&g_is32, 1);
    }
}

__device__ __forceinline__ int load_idx(const void* ei, int pos, int is32, int n) {
    int v;
    if (is32) v = ((const int*)ei)[pos];
    else      v = (int)((const long long*)ei)[pos];
    return v < 0 ? 0 : (v >= n ? n - 1 : v);
}

__global__ void k_edge_deg(const void* __restrict__ ei,
                           const float* __restrict__ w, int E, int n) {
    int e = blockIdx.x * blockDim.x + threadIdx.x;
    if (e < E) {
        int is32 = g_is32;
        int dst = load_idx(ei, E + e, is32, n);
        atomicAdd(&g_deg[dst], w[e]);
        atomicAdd(&g_counts[dst], 1);
    }
}

// --- exclusive scan of g_counts -> g_row_start; also computes dis ---
__global__ void k_scan_local(int n) {
    __shared__ int sh[1024];
    int tid = threadIdx.x;
    int gid = blockIdx.x * 1024 + tid;
    int v = (gid < n) ? g_counts[gid] : 0;
    if (gid < n) g_dis[gid] = rsqrtf(g_deg[gid]);    // deg >= 1 always
    sh[tid] = v;
    __syncthreads();
    for (int off = 1; off < 1024; off <<= 1) {
        int t = (tid >= off) ? sh[tid - off] : 0;
        __syncthreads();
        sh[tid] += t;
        __syncthreads();
    }
    if (gid < n) g_row_start[gid] = sh[tid] - v;
    if (tid == 1023) g_block_sums[blockIdx.x] = sh[1023];
}

__global__ void k_scan_top(int nb) {
    __shared__ int sh[1024];
    int tid = threadIdx.x;
    int v = (tid < nb) ? g_block_sums[tid] : 0;
    sh[tid] = v;
    __syncthreads();
    for (int off = 1; off < 1024; off <<= 1) {
        int t = (tid >= off) ? sh[tid - off] : 0;
        __syncthreads();
        sh[tid] += t;
        __syncthreads();
    }
    if (tid < nb) g_block_sums[tid] = sh[tid] - v;
}

__global__ void k_scan_add(int n) {
    int gid = blockIdx.x * 1024 + threadIdx.x;
    if (gid < n) {
        int s = g_row_start[gid] + g_block_sums[blockIdx.x];
        g_row_start[gid] = s;
        g_cursor[gid]    = s;
    }
}

// --- CSR-by-dst scatter with packed (src, norm) 8B record ---
__global__ void k_build(const void* __restrict__ ei,
                        const float* __restrict__ w, int E, int n) {
    int e = blockIdx.x * blockDim.x + threadIdx.x;
    if (e < E) {
        int is32 = g_is32;
        int s = load_idx(ei, e, is32, n);
        int d = load_idx(ei, E + e, is32, n);
        int pos = atomicAdd(&g_cursor[d], 1);
        float nm = g_dis[s] * w[e] * g_dis[d];
        g_edge[pos] = make_int2(s, __float_as_int(nm));
    }
}

// --- aggregation: one warp per node, split into two 16-lane edge groups ---
// Each lane loads 8B (2 half2 = 4 cols); group handles alternate edges.
// io_mode: 0/2 read g_hA, 1 read g_hB. Writes g_agg16.
__global__ void k_gather(int io_mode, int n) {
    const __half2* hin = (io_mode == 1) ? g_hB : g_hA;
    int node = (blockIdx.x * blockDim.x + threadIdx.x) >> 5;
    if (node >= n) return;
    int lane = threadIdx.x & 31;
    int g = lane >> 4;          // edge group 0/1
    int l = lane & 15;          // column slot: uint2 index within row

    const uint2* hv = (const uint2*)hin;   // row = 16 uint2 (128B)
    float a0 = 0.f, a1 = 0.f, a2 = 0.f, a3 = 0.f;

    if (g == 0) {   // self-loop term handled by group 0 only
        float dd = g_dis[node];
        dd *= dd;
        uint2 sv = hv[node * 16 + l];
        float2 f0 = __half22float2(*reinterpret_cast<__half2*>(&sv.x));
        float2 f1 = __half22float2(*reinterpret_cast<__half2*>(&sv.y));
        a0 = f0.x * dd; a1 = f0.y * dd; a2 = f1.x * dd; a3 = f1.y * dd;
    }

    int e   = g_row_start[node] + g;
    int end = g_cursor[node];
    for (; e + 3 <= end; e += 4) {   // two edges per group per iter
        int2 r0 = g_edge[e];
        int2 r1 = g_edge[e + 2];
        uint2 v0 = hv[r0.x * 16 + l];
        uint2 v1 = hv[r1.x * 16 + l];
        float n0 = __int_as_float(r0.y);
        float n1 = __int_as_float(r1.y);
        float2 p0 = __half22float2(*reinterpret_cast<__half2*>(&v0.x));
        float2 p1 = __half22float2(*reinterpret_cast<__half2*>(&v0.y));
        float2 q0 = __half22float2(*reinterpret_cast<__half2*>(&v1.x));
        float2 q1 = __half22float2(*reinterpret_cast<__half2*>(&v1.y));
        a0 += p0.x * n0; a1 += p0.y * n0; a2 += p1.x * n0; a3 += p1.y * n0;
        a0 += q0.x * n1; a1 += q0.y * n1; a2 += q1.x * n1; a3 += q1.y * n1;
    }
    if (e < end) {
        int2 r0 = g_edge[e];
        uint2 v0 = hv[r0.x * 16 + l];
        float n0 = __int_as_float(r0.y);
        float2 p0 = __half22float2(*reinterpret_cast<__half2*>(&v0.x));
        float2 p1 = __half22float2(*reinterpret_cast<__half2*>(&v0.y));
        a0 += p0.x * n0; a1 += p0.y * n0; a2 += p1.x * n0; a3 += p1.y * n0;
    }

    // combine the two groups
    a0 += __shfl_down_sync(0xffffffffu, a0, 16);
    a1 += __shfl_down_sync(0xffffffffu, a1, 16);
    a2 += __shfl_down_sync(0xffffffffu, a2, 16);
    a3 += __shfl_down_sync(0xffffffffu, a3, 16);

    if (g == 0) {
        __half2 o0 = __floats2half2_rn(a0, a1);
        __half2 o1 = __floats2half2_rn(a2, a3);
        uint2 st;
        st.x = *reinterpret_cast<unsigned*>(&o0);
        st.y = *reinterpret_cast<unsigned*>(&o1);
        ((uint2*)g_agg16)[node * 16 + l] = st;
    }
}

// --- tensor-core GEMM (agg16 @ W) + bias (+relu) ---
// 256 thr = 8 warps; block does 128 rows x 64 cols. Warp w owns rows [w*16, w*16+16).
// A fragments load straight from global g_agg16 (row-major half, ld=64).
// io_mode: 0 -> g_hB (relu), 1 -> g_hA (relu), 2 -> outf fp32 (no relu)
__global__ void __launch_bounds__(256) k_gemm(
    const float* __restrict__ W, const float* __restrict__ b,
    float* __restrict__ outf, int io_mode, int n)
{
    __half2* outh = (io_mode == 0) ? g_hB : (io_mode == 1 ? g_hA : nullptr);
    int relu = (io_mode != 2);

    __shared__ __half Wh[64 * 64];          // 8KB, row-major [k][c], ld=64
    __shared__ float  Cbuf[8][16][72];      // 36KB, per-warp 16x64 (+pad)

    int tid  = threadIdx.x;
    int warp = tid >> 5;
    int lane = tid & 31;
    int row0 = blockIdx.x * 128;

    for (int i = tid; i < 4096; i += 256)
        Wh[i] = __float2half(W[i]);
    __syncthreads();

    const __half* ABase = reinterpret_cast<const __half*>(g_agg16);
    int rbase = row0 + warp * 16;           // padding rows in g_agg16 stay zero

    wmma::fragment<wmma::accumulator, 16, 16, 16, float> c[4];
#pragma unroll
    for (int j = 0; j < 4; j++) wmma::fill_fragment(c[j], 0.0f);

#pragma unroll
    for (int kt = 0; kt < 4; kt++) {
        wmma::fragment<wmma::matrix_a, 16, 16, 16, __half, wmma::row_major> a;
        wmma::load_matrix_sync(a, ABase + rbase * 64 + kt * 16, 64);
#pragma unroll
        for (int j = 0; j < 4; j++) {
            wmma::fragment<wmma::matrix_b, 16, 16, 16, __half, wmma::row_major> bf;
            wmma::load_matrix_sync(bf, &Wh[(kt * 16) * 64 + j * 16], 64);
            wmma::mma_sync(c[j], a, bf, c[j]);
        }
    }
#pragma unroll
    for (int j = 0; j < 4; j++)
        wmma::store_matrix_sync(&Cbuf[warp][0][j * 16], c[j], 72, wmma::mem_row_major);
    __syncwarp();

    // epilogue: each lane handles one row-half (16 rows x 2 halves = 32 lanes)
    int r    = lane & 15;
    int half = lane >> 4;          // cols [half*32, half*32+32)
    int grow = rbase + r;
    if (grow < n) {
        int cbase = half * 32;
#pragma unroll
        for (int j = 0; j < 8; j++) {
            int cc = cbase + j * 4;
            float4 v = *(const float4*)&Cbuf[warp][r][cc];
            float4 bv = *(const float4*)&b[cc];
            v.x += bv.x; v.y += bv.y; v.z += bv.z; v.w += bv.w;
            if (relu) {
                v.x = fmaxf(v.x, 0.f); v.y = fmaxf(v.y, 0.f);
                v.z = fmaxf(v.z, 0.f); v.w = fmaxf(v.w, 0.f);
            }
            if (outh) {
                outh[grow * 32 + (cc >> 1)]     = __floats2half2_rn(v.x, v.y);
                outh[grow * 32 + (cc >> 1) + 1] = __floats2half2_rn(v.z, v.w);
            } else {
                *(float4*)&outf[grow * 64 + cc] = v;
            }
        }
    }
}

// ---------------------------------------------------------------------------
extern "C" void kernel_launch(void* const* d_in, const int* in_sizes, int n_in,
                              void* d_out, int out_size) {
    const float* x  = (const float*)d_in[0];
    const void*  ei = d_in[1];
    const float* w  = (const float*)d_in[2];
    const float* W1 = (const float*)d_in[3];
    const float* b1 = (const float*)d_in[4];
    const float* W2 = (const float*)d_in[5];
    const float* b2 = (const float*)d_in[6];
    const float* W3 = (const float*)d_in[7];
    const float* b3 = (const float*)d_in[8];
    float* out = (float*)d_out;

    int n = in_sizes[0] / D;      // 100000
    int E = in_sizes[1] / 2;      // 1600000

    const int tb = 256;
    int nv = n * 32;                         // half2 elements of feature matrix
    int nblk_p = (nv + tb - 1) / tb;
    int nblk_e = (E + tb - 1) / tb;
    int nb = (n + 1023) / 1024;

    k_prep<<<nblk_p, tb>>>(x, (const long long*)ei, n, nv);
    k_edge_deg<<<nblk_e, tb>>>(ei, w, E, n);
    k_scan_local<<<nb, 1024>>>(n);
    k_scan_top<<<1, 1024>>>(nb);
    k_scan_add<<<nb, 1024>>>(n);
    k_build<<<nblk_e, tb>>>(ei, w, E, n);

    int gblocks = (n * 32 + tb - 1) / tb;   // one warp per node
    int mblocks = (n + 127) / 128;

    // layer1: hA -> agg -> hB ; layer2: hB -> agg -> hA ; layer3: hA -> out
    k_gather<<<gblocks, tb>>>(0, n);
    k_gemm<<<mblocks, 256>>>(W1, b1, nullptr, 0, n);
    k_gather<<<gblocks, tb>>>(1, n);
    k_gemm<<<mblocks, 256>>>(W2, b2, nullptr, 1, n);
    k_gather<<<gblocks, tb>>>(0, n);
    k_gemm<<<mblocks, 256>>>(W3, b3, out, 2, n);
}